// round 6
// baseline (speedup 1.0000x reference)
#include <cuda_runtime.h>
#include <math.h>

#define NMAX 100000
#define EMAX 1600000
#define C_IN 64
#define C_OUT 128
#define RPB 32
#define NB_SCAN ((NMAX + 1023) / 1024)

// Scratch (device globals — no allocations allowed)
__device__ float g_x0[(size_t)NMAX * C_IN];
__device__ float g_x1[(size_t)NMAX * C_IN];
__device__ float g_dinv[NMAX];
__device__ int   g_cnt[NMAX];
__device__ int   g_rowstart[NMAX + 1];
__device__ int2  g_edge[EMAX];                // {srcid, coef bits}
__device__ int   g_blocksum[NB_SCAN];
__device__ int   g_blockoff[NB_SCAN];

__device__ __forceinline__ int clampi(int v, int lo, int hi) {
    return v < lo ? lo : (v > hi ? hi : v);
}

// ---- f32x2 packed math helpers ----
__device__ __forceinline__ unsigned long long pack2(float lo, float hi) {
    unsigned long long r;
    asm("mov.b64 %0, {%1, %2};" : "=l"(r) : "f"(lo), "f"(hi));
    return r;
}
__device__ __forceinline__ void unpack2(unsigned long long v, float& lo, float& hi) {
    asm("mov.b64 {%0, %1}, %2;" : "=f"(lo), "=f"(hi) : "l"(v));
}
#define FMA_F32X2(d, a, b, c) \
    asm("fma.rn.f32x2 %0, %1, %2, %3;" : "=l"(d) : "l"(a), "l"(b), "l"(c))
#define ADD_F32X2(d, a, b) \
    asm("add.rn.f32x2 %0, %1, %2;" : "=l"(d) : "l"(a), "l"(b))

// ---------------- CSR build ----------------
__global__ void zero_cnt_kernel(int n) {
    int i = blockIdx.x * blockDim.x + threadIdx.x;
    if (i < n) g_cnt[i] = 0;
}
__global__ void count_kernel(const int* __restrict__ dst, int e, int n) {
    int i = blockIdx.x * blockDim.x + threadIdx.x;
    if (i < e) atomicAdd(&g_cnt[clampi(dst[i], 0, n - 1)], 1);
}
__global__ void dinv_kernel(int n) {
    int i = blockIdx.x * blockDim.x + threadIdx.x;
    if (i < n) g_dinv[i] = rsqrtf((float)g_cnt[i] + 1.0f);
}
__global__ void __launch_bounds__(1024) scan1_kernel(int n) {
    __shared__ int sm[1024];
    int i = blockIdx.x * 1024 + threadIdx.x;
    int v = (i < n) ? g_cnt[i] : 0;
    sm[threadIdx.x] = v;
    __syncthreads();
    #pragma unroll
    for (int off = 1; off < 1024; off <<= 1) {
        int t = (threadIdx.x >= off) ? sm[threadIdx.x - off] : 0;
        __syncthreads();
        sm[threadIdx.x] += t;
        __syncthreads();
    }
    if (i < n) g_rowstart[i] = sm[threadIdx.x] - v;
    if (threadIdx.x == 1023) g_blocksum[blockIdx.x] = sm[1023];
}
__global__ void scan2_kernel(int nb, int n) {
    if (threadIdx.x == 0 && blockIdx.x == 0) {
        int run = 0;
        for (int b = 0; b < nb; b++) { g_blockoff[b] = run; run += g_blocksum[b]; }
        g_rowstart[n] = run;
    }
}
__global__ void __launch_bounds__(1024) scan3_kernel(int n) {
    int i = blockIdx.x * 1024 + threadIdx.x;
    if (i < n) g_rowstart[i] += g_blockoff[blockIdx.x];
}
__global__ void fill_kernel(const int* __restrict__ src,
                            const int* __restrict__ dst, int e, int n) {
    int i = blockIdx.x * blockDim.x + threadIdx.x;
    if (i >= e) return;
    int s = clampi(src[i], 0, n - 1);
    int d = clampi(dst[i], 0, n - 1);
    int pos = g_rowstart[d] + atomicAdd(&g_cnt[d], 1);
    g_edge[pos] = make_int2(s, __float_as_int(g_dinv[s] * g_dinv[d]));
}

// ---------------- fused layer: gather + GEMM + GLU + residual -------------
// Block = 32 nodes, 256 threads.
// Phase A: warp per 4 nodes gathers y = dinv^2*x + sum(coef*x[src]) into smem
//          stored packed-duplicated for f32x2.
// Phase B: thread t computes h cols (c, c+64) packed for 8 rows, then GLU.
__global__ void __launch_bounds__(256, 1)
layer_kernel(const float* __restrict__ xin, float* __restrict__ xout,
             const float* __restrict__ W, const float* __restrict__ b, int n) {
    __shared__ ulonglong2 ys[RPB][32];            // 16 KB: (y2k,y2k),(y2k+1,y2k+1)
    __shared__ unsigned long long wsp[C_IN][64];  // 32 KB: (W[k][c], W[k][c+64])

    const int tid = threadIdx.x;
    const int w = tid >> 5, lane = tid & 31;
    const int row0 = blockIdx.x * RPB;

    // stage W packed
    const float4* W4 = reinterpret_cast<const float4*>(W);
    #pragma unroll
    for (int idx = tid; idx < 1024; idx += 256) {
        int k = idx >> 4, c4 = (idx & 15) << 2;
        float4 wa = W4[k * 32 + (c4 >> 2)];
        float4 wb = W4[k * 32 + 16 + (c4 >> 2)];
        wsp[k][c4 + 0] = pack2(wa.x, wb.x);
        wsp[k][c4 + 1] = pack2(wa.y, wb.y);
        wsp[k][c4 + 2] = pack2(wa.z, wb.z);
        wsp[k][c4 + 3] = pack2(wa.w, wb.w);
    }

    // Phase A: gather (lane holds channels 2*lane, 2*lane+1)
    const float2* x2 = reinterpret_cast<const float2*>(xin);
    #pragma unroll
    for (int i = 0; i < 4; i++) {
        int r = w * 4 + i;
        int node = row0 + r;
        float2 acc = make_float2(0.0f, 0.0f);
        if (node < n) {
            float dv = g_dinv[node], s2 = dv * dv;
            acc = x2[(size_t)node * 32 + lane];
            acc.x *= s2; acc.y *= s2;
            int e0 = g_rowstart[node], e1 = g_rowstart[node + 1];
            for (int base = e0; base < e1; base += 32) {
                int m = e1 - base; if (m > 32) m = 32;
                int sid = 0; float cf = 0.0f;
                if (lane < m) {
                    int2 ed = g_edge[base + lane];
                    sid = ed.x; cf = __int_as_float(ed.y);
                }
                #pragma unroll 4
                for (int t = 0; t < m; t++) {
                    int   s = __shfl_sync(0xffffffffu, sid, t);
                    float c = __shfl_sync(0xffffffffu, cf,  t);
                    float2 v = x2[(size_t)s * 32 + lane];
                    acc.x = fmaf(v.x, c, acc.x);
                    acc.y = fmaf(v.y, c, acc.y);
                }
            }
        }
        ys[r][lane] = make_ulonglong2(pack2(acc.x, acc.x), pack2(acc.y, acc.y));
    }
    __syncthreads();

    // Phase B: packed GEMM + GLU + residual
    const int c = tid & 63;
    const int q = tid >> 6;     // 4 row-groups of 8
    unsigned long long wp[C_IN];
    #pragma unroll
    for (int k = 0; k < C_IN; k++) wp[k] = wsp[k][c];
    const unsigned long long bb = pack2(b[c], b[c + 64]);

    #pragma unroll
    for (int rr = 0; rr < 8; rr++) {
        int r = q * 8 + rr;
        int row = row0 + r;
        unsigned long long a0 = bb, a1 = 0ull;
        #pragma unroll
        for (int k2 = 0; k2 < 32; k2++) {
            ulonglong2 y = ys[r][k2];
            FMA_F32X2(a0, y.x, wp[2 * k2 + 0], a0);
            FMA_F32X2(a1, y.y, wp[2 * k2 + 1], a1);
        }
        unsigned long long at;
        ADD_F32X2(at, a0, a1);
        float av, gv;
        unpack2(at, av, gv);
        if (row < n) {
            float sig = 1.0f / (1.0f + expf(-gv));
            xout[(size_t)row * C_IN + c] =
                fmaf(av, sig, xin[(size_t)row * C_IN + c]);
        }
    }
}

extern "C" void kernel_launch(void* const* d_in, const int* in_sizes, int n_in,
                              void* d_out, int out_size) {
    // Identify inputs by SIZE:
    //   x: == out_size (6.4M f32); edge_index: largest rest (3.2M i32);
    //   Ws: next (24576 f32); bs: smallest (384 f32)
    const float* x = nullptr; const float* Ws = nullptr; const float* bs = nullptr;
    const int* ei = nullptr;
    int ei_elems = 0, Ws_elems = 0;
    int used[16] = {0};
    for (int i = 0; i < n_in; i++)
        if (!x && in_sizes[i] == out_size) { x = (const float*)d_in[i]; used[i] = 1; break; }
    {
        int best = -1, bsz = -1;
        for (int i = 0; i < n_in; i++)
            if (!used[i] && in_sizes[i] > bsz) { bsz = in_sizes[i]; best = i; }
        ei = (const int*)d_in[best]; ei_elems = bsz; used[best] = 1;
    }
    {
        int best = -1, bsz = -1;
        for (int i = 0; i < n_in; i++)
            if (!used[i] && in_sizes[i] > bsz) { bsz = in_sizes[i]; best = i; }
        Ws = (const float*)d_in[best]; Ws_elems = bsz; used[best] = 1;
    }
    for (int i = 0; i < n_in; i++)
        if (!used[i]) { bs = (const float*)d_in[i]; used[i] = 1; break; }

    const int n = out_size / C_IN;
    const int e = ei_elems / 2;
    const int L = Ws_elems / (C_IN * C_OUT);
    const int* src = ei;
    const int* dst = ei + e;
    const int nb = (n + 1023) / 1024;

    float *x0, *x1;
    cudaGetSymbolAddress((void**)&x0, g_x0);
    cudaGetSymbolAddress((void**)&x1, g_x1);

    // ---- CSR build (once per call) ----
    zero_cnt_kernel<<<(n + 255) / 256, 256>>>(n);
    count_kernel<<<(e + 255) / 256, 256>>>(dst, e, n);
    dinv_kernel<<<(n + 255) / 256, 256>>>(n);
    scan1_kernel<<<nb, 1024>>>(n);
    scan2_kernel<<<1, 32>>>(nb, n);
    scan3_kernel<<<nb, 1024>>>(n);
    zero_cnt_kernel<<<(n + 255) / 256, 256>>>(n);
    fill_kernel<<<(e + 255) / 256, 256>>>(src, dst, e, n);

    // ---- layers (fully fused) ----
    const int grid = (n + RPB - 1) / RPB;
    const float* xin = x;
    for (int l = 0; l < L; l++) {
        float* xout = (l == L - 1) ? (float*)d_out : ((l & 1) ? x1 : x0);
        layer_kernel<<<grid, 256>>>(
            xin, xout, Ws + (size_t)l * C_IN * C_OUT, bs + (size_t)l * C_OUT, n);
        xin = xout;
    }
}

// round 7
// speedup vs baseline: 2.3409x; 2.3409x over previous
#include <cuda_runtime.h>
#include <math.h>

#define NMAX 100000
#define EMAX 1600000
#define C_IN 64
#define C_OUT 128
#define RPB 32
#define NB_SCAN ((NMAX + 1023) / 1024)

// Scratch (device globals — no allocations allowed)
__device__ float g_y[(size_t)NMAX * C_IN];
__device__ float g_x0[(size_t)NMAX * C_IN];
__device__ float g_x1[(size_t)NMAX * C_IN];
__device__ float g_dinv[NMAX];
__device__ int   g_cnt[NMAX];
__device__ int   g_rowstart[NMAX + 1];
__device__ int2  g_edge[EMAX];                // {srcid, coef bits}
__device__ int   g_blocksum[NB_SCAN];
__device__ int   g_blockoff[NB_SCAN];

__device__ __forceinline__ int clampi(int v, int lo, int hi) {
    return v < lo ? lo : (v > hi ? hi : v);
}

// ---- f32x2 packed math helpers ----
__device__ __forceinline__ unsigned long long pack2(float lo, float hi) {
    unsigned long long r;
    asm("mov.b64 %0, {%1, %2};" : "=l"(r) : "f"(lo), "f"(hi));
    return r;
}
__device__ __forceinline__ void unpack2(unsigned long long v, float& lo, float& hi) {
    asm("mov.b64 {%0, %1}, %2;" : "=f"(lo), "=f"(hi) : "l"(v));
}
#define FMA_F32X2(d, a, b, c) \
    asm("fma.rn.f32x2 %0, %1, %2, %3;" : "=l"(d) : "l"(a), "l"(b), "l"(c))
#define ADD_F32X2(d, a, b) \
    asm("add.rn.f32x2 %0, %1, %2;" : "=l"(d) : "l"(a), "l"(b))

// ---------------- CSR build ----------------
__global__ void zero_cnt_kernel(int n) {
    int i = blockIdx.x * blockDim.x + threadIdx.x;
    if (i < n) g_cnt[i] = 0;
}
__global__ void count_kernel(const int* __restrict__ dst, int e, int n) {
    int i = blockIdx.x * blockDim.x + threadIdx.x;
    if (i < e) atomicAdd(&g_cnt[clampi(dst[i], 0, n - 1)], 1);
}
__global__ void dinv_kernel(int n) {
    int i = blockIdx.x * blockDim.x + threadIdx.x;
    if (i < n) g_dinv[i] = rsqrtf((float)g_cnt[i] + 1.0f);
}
__global__ void __launch_bounds__(1024) scan1_kernel(int n) {
    __shared__ int sm[1024];
    int i = blockIdx.x * 1024 + threadIdx.x;
    int v = (i < n) ? g_cnt[i] : 0;
    sm[threadIdx.x] = v;
    __syncthreads();
    #pragma unroll
    for (int off = 1; off < 1024; off <<= 1) {
        int t = (threadIdx.x >= off) ? sm[threadIdx.x - off] : 0;
        __syncthreads();
        sm[threadIdx.x] += t;
        __syncthreads();
    }
    if (i < n) g_rowstart[i] = sm[threadIdx.x] - v;
    if (threadIdx.x == 1023) g_blocksum[blockIdx.x] = sm[1023];
}
// single-warp scan over block sums (nb <= 128 handled in chunks of 32)
__global__ void scan2_kernel(int nb, int n) {
    int lane = threadIdx.x;
    int carry = 0;
    for (int base = 0; base < nb; base += 32) {
        int v = (base + lane < nb) ? g_blocksum[base + lane] : 0;
        int incl = v;
        #pragma unroll
        for (int off = 1; off < 32; off <<= 1) {
            int t = __shfl_up_sync(0xffffffffu, incl, off);
            if (lane >= off) incl += t;
        }
        if (base + lane < nb) g_blockoff[base + lane] = carry + incl - v;
        carry += __shfl_sync(0xffffffffu, incl, 31);
    }
    if (lane == 0) g_rowstart[n] = carry;
}
__global__ void __launch_bounds__(1024) scan3_kernel(int n) {
    int i = blockIdx.x * 1024 + threadIdx.x;
    if (i < n) g_rowstart[i] += g_blockoff[blockIdx.x];
}
__global__ void fill_kernel(const int* __restrict__ src,
                            const int* __restrict__ dst, int e, int n) {
    int i = blockIdx.x * blockDim.x + threadIdx.x;
    if (i >= e) return;
    int s = clampi(src[i], 0, n - 1);
    int d = clampi(dst[i], 0, n - 1);
    int pos = g_rowstart[d] + atomicAdd(&g_cnt[d], 1);
    g_edge[pos] = make_int2(s, __float_as_int(g_dinv[s] * g_dinv[d]));
}

// ---------------- aggregate in x-space (64 ch) ----------------
// one warp per node; lane holds float2 = cols 2L..2L+1  (unchanged from R5)
__global__ void __launch_bounds__(256)
agg_kernel(const float* __restrict__ xin, int n) {
    int node = (blockIdx.x * blockDim.x + threadIdx.x) >> 5;
    int lane = threadIdx.x & 31;
    if (node >= n) return;

    const float2* x2 = reinterpret_cast<const float2*>(xin);
    float dv = g_dinv[node];
    float s2 = dv * dv;
    float2 acc = x2[(size_t)node * 32 + lane];
    acc.x *= s2; acc.y *= s2;

    int r0 = g_rowstart[node];
    int r1 = g_rowstart[node + 1];
    for (int base = r0; base < r1; base += 32) {
        int m = r1 - base; if (m > 32) m = 32;
        int sid = 0; float cf = 0.0f;
        if (lane < m) {
            int2 ed = g_edge[base + lane];
            sid = ed.x; cf = __int_as_float(ed.y);
        }
        #pragma unroll 4
        for (int t = 0; t < m; t++) {
            int   s = __shfl_sync(0xffffffffu, sid, t);
            float c = __shfl_sync(0xffffffffu, cf,  t);
            float2 v = x2[(size_t)s * 32 + lane];
            acc.x = fmaf(v.x, c, acc.x);
            acc.y = fmaf(v.y, c, acc.y);
        }
    }
    reinterpret_cast<float2*>(g_y)[(size_t)node * 32 + lane] = acc;
}

// ---------------- packed GEMM + bias + GLU + residual ----------------
// 128 threads: thread j owns col pair (c, c+64), c = j&63; row-group q = j>>6
// handles 16 of the block's 32 rows. Weights packed in regs; y packed-dup in smem.
__global__ void __launch_bounds__(128)
gemm_glu_kernel(const float* __restrict__ xin, float* __restrict__ xout,
                const float* __restrict__ W, const float* __restrict__ b,
                int n) {
    __shared__ unsigned long long ysp[RPB][C_IN];   // 16 KB: pack2(y,y)

    const int j = threadIdx.x;
    const int c = j & 63;
    const int q = j >> 6;                 // 0 or 1
    const int row0 = blockIdx.x * RPB;

    // stage y rows, duplicated into both packed lanes
    #pragma unroll
    for (int t = j; t < RPB * C_IN; t += 128) {
        int r = t >> 6, k = t & 63;
        int row = row0 + r;
        float v = (row < n) ? g_y[(size_t)row * C_IN + k] : 0.0f;
        ysp[r][k] = pack2(v, v);
    }

    // weight column pair into registers (L1/L2 resident after first wave)
    unsigned long long wp[C_IN];
    #pragma unroll
    for (int k = 0; k < C_IN; k++)
        wp[k] = pack2(W[k * C_OUT + c], W[k * C_OUT + c + 64]);
    const unsigned long long bb = pack2(b[c], b[c + 64]);

    __syncthreads();

    #pragma unroll 2
    for (int rr = 0; rr < RPB / 2; rr++) {
        int r = q * (RPB / 2) + rr;
        int row = row0 + r;
        unsigned long long a0 = bb, a1 = 0ull;
        #pragma unroll
        for (int k = 0; k < C_IN; k += 2) {
            FMA_F32X2(a0, ysp[r][k + 0], wp[k + 0], a0);
            FMA_F32X2(a1, ysp[r][k + 1], wp[k + 1], a1);
        }
        unsigned long long at;
        ADD_F32X2(at, a0, a1);
        float av, gv;
        unpack2(at, av, gv);
        if (row < n) {
            float sig = 1.0f / (1.0f + expf(-gv));
            xout[(size_t)row * C_IN + c] =
                fmaf(av, sig, xin[(size_t)row * C_IN + c]);
        }
    }
}

extern "C" void kernel_launch(void* const* d_in, const int* in_sizes, int n_in,
                              void* d_out, int out_size) {
    // Identify inputs by SIZE:
    //   x: == out_size (6.4M f32); edge_index: largest rest (3.2M i32);
    //   Ws: next (24576 f32); bs: smallest (384 f32)
    const float* x = nullptr; const float* Ws = nullptr; const float* bs = nullptr;
    const int* ei = nullptr;
    int ei_elems = 0, Ws_elems = 0;
    int used[16] = {0};
    for (int i = 0; i < n_in; i++)
        if (!x && in_sizes[i] == out_size) { x = (const float*)d_in[i]; used[i] = 1; break; }
    {
        int best = -1, bsz = -1;
        for (int i = 0; i < n_in; i++)
            if (!used[i] && in_sizes[i] > bsz) { bsz = in_sizes[i]; best = i; }
        ei = (const int*)d_in[best]; ei_elems = bsz; used[best] = 1;
    }
    {
        int best = -1, bsz = -1;
        for (int i = 0; i < n_in; i++)
            if (!used[i] && in_sizes[i] > bsz) { bsz = in_sizes[i]; best = i; }
        Ws = (const float*)d_in[best]; Ws_elems = bsz; used[best] = 1;
    }
    for (int i = 0; i < n_in; i++)
        if (!used[i]) { bs = (const float*)d_in[i]; used[i] = 1; break; }

    const int n = out_size / C_IN;
    const int e = ei_elems / 2;
    const int L = Ws_elems / (C_IN * C_OUT);
    const int* src = ei;
    const int* dst = ei + e;
    const int nb = (n + 1023) / 1024;

    float *x0, *x1;
    cudaGetSymbolAddress((void**)&x0, g_x0);
    cudaGetSymbolAddress((void**)&x1, g_x1);

    // ---- CSR build (once per call) ----
    zero_cnt_kernel<<<(n + 255) / 256, 256>>>(n);
    count_kernel<<<(e + 255) / 256, 256>>>(dst, e, n);
    dinv_kernel<<<(n + 255) / 256, 256>>>(n);
    scan1_kernel<<<nb, 1024>>>(n);
    scan2_kernel<<<1, 32>>>(nb, n);
    scan3_kernel<<<nb, 1024>>>(n);
    zero_cnt_kernel<<<(n + 255) / 256, 256>>>(n);
    fill_kernel<<<(e + 255) / 256, 256>>>(src, dst, e, n);

    // ---- layers ----
    const float* xin = x;
    for (int l = 0; l < L; l++) {
        float* xout = (l == L - 1) ? (float*)d_out : ((l & 1) ? x1 : x0);
        agg_kernel<<<(n * 32 + 255) / 256, 256>>>(xin, n);
        gemm_glu_kernel<<<(n + RPB - 1) / RPB, 128>>>(
            xin, xout, Ws + (size_t)l * C_IN * C_OUT, bs + (size_t)l * C_OUT, n);
        xin = xout;
    }
}

// round 8
// speedup vs baseline: 2.3688x; 1.0119x over previous
#include <cuda_runtime.h>
#include <math.h>

#define NMAX 100000
#define EMAX 1600000
#define C_IN 64
#define C_OUT 128
#define RPB 64
#define NB_SCAN ((NMAX + 1023) / 1024)

// Scratch (device globals — no allocations allowed)
__device__ float g_y[(size_t)NMAX * C_IN];
__device__ float g_x0[(size_t)NMAX * C_IN];
__device__ float g_x1[(size_t)NMAX * C_IN];
__device__ float g_dinv[NMAX];
__device__ int   g_cnt[NMAX];
__device__ int   g_rowstart[NMAX + 1];
__device__ int2  g_edge[EMAX];                // {srcid, coef bits}
__device__ int   g_blocksum[NB_SCAN];
__device__ int   g_blockoff[NB_SCAN];

__device__ __forceinline__ int clampi(int v, int lo, int hi) {
    return v < lo ? lo : (v > hi ? hi : v);
}

// ---- f32x2 packed math helpers ----
__device__ __forceinline__ unsigned long long pack2(float lo, float hi) {
    unsigned long long r;
    asm("mov.b64 %0, {%1, %2};" : "=l"(r) : "f"(lo), "f"(hi));
    return r;
}
__device__ __forceinline__ void unpack2(unsigned long long v, float& lo, float& hi) {
    asm("mov.b64 {%0, %1}, %2;" : "=f"(lo), "=f"(hi) : "l"(v));
}
#define FMA_F32X2(d, a, b, c) \
    asm("fma.rn.f32x2 %0, %1, %2, %3;" : "=l"(d) : "l"(a), "l"(b), "l"(c))
#define ADD_F32X2(d, a, b) \
    asm("add.rn.f32x2 %0, %1, %2;" : "=l"(d) : "l"(a), "l"(b))

// ---------------- CSR build ----------------
__global__ void zero_cnt_kernel(int n) {
    int i = blockIdx.x * blockDim.x + threadIdx.x;
    if (i < n) g_cnt[i] = 0;
}
__global__ void count_kernel(const int* __restrict__ dst, int e, int n) {
    int i = blockIdx.x * blockDim.x + threadIdx.x;
    if (i < e) atomicAdd(&g_cnt[clampi(dst[i], 0, n - 1)], 1);
}
__global__ void dinv_kernel(int n) {
    int i = blockIdx.x * blockDim.x + threadIdx.x;
    if (i < n) g_dinv[i] = rsqrtf((float)g_cnt[i] + 1.0f);
}
__global__ void __launch_bounds__(1024) scan1_kernel(int n) {
    __shared__ int sm[1024];
    int i = blockIdx.x * 1024 + threadIdx.x;
    int v = (i < n) ? g_cnt[i] : 0;
    sm[threadIdx.x] = v;
    __syncthreads();
    #pragma unroll
    for (int off = 1; off < 1024; off <<= 1) {
        int t = (threadIdx.x >= off) ? sm[threadIdx.x - off] : 0;
        __syncthreads();
        sm[threadIdx.x] += t;
        __syncthreads();
    }
    if (i < n) g_rowstart[i] = sm[threadIdx.x] - v;
    if (threadIdx.x == 1023) g_blocksum[blockIdx.x] = sm[1023];
}
// single-warp scan over block sums
__global__ void scan2_kernel(int nb, int n) {
    int lane = threadIdx.x;
    int carry = 0;
    for (int base = 0; base < nb; base += 32) {
        int v = (base + lane < nb) ? g_blocksum[base + lane] : 0;
        int incl = v;
        #pragma unroll
        for (int off = 1; off < 32; off <<= 1) {
            int t = __shfl_up_sync(0xffffffffu, incl, off);
            if (lane >= off) incl += t;
        }
        if (base + lane < nb) g_blockoff[base + lane] = carry + incl - v;
        carry += __shfl_sync(0xffffffffu, incl, 31);
    }
    if (lane == 0) g_rowstart[n] = carry;
}
__global__ void __launch_bounds__(1024) scan3_kernel(int n) {
    int i = blockIdx.x * 1024 + threadIdx.x;
    if (i < n) g_rowstart[i] += g_blockoff[blockIdx.x];
}
__global__ void fill_kernel(const int* __restrict__ src,
                            const int* __restrict__ dst, int e, int n) {
    int i = blockIdx.x * blockDim.x + threadIdx.x;
    if (i >= e) return;
    int s = clampi(src[i], 0, n - 1);
    int d = clampi(dst[i], 0, n - 1);
    int pos = g_rowstart[d] + atomicAdd(&g_cnt[d], 1);
    g_edge[pos] = make_int2(s, __float_as_int(g_dinv[s] * g_dinv[d]));
}

// ---------------- aggregate in x-space (64 ch) ----------------
// one warp per node; half-warps process edges t, t+1 in parallel.
// lane = half*16 + hl; each half covers the full 64-ch row via float4 (16 x 16B).
__global__ void __launch_bounds__(256)
agg_kernel(const float* __restrict__ xin, int n) {
    int node = (blockIdx.x * blockDim.x + threadIdx.x) >> 5;
    if (node >= n) return;
    int lane = threadIdx.x & 31;
    int half = lane >> 4;
    int hl = lane & 15;

    const float4* x4 = reinterpret_cast<const float4*>(xin);
    float4 acc = make_float4(0.f, 0.f, 0.f, 0.f);

    int e0 = g_rowstart[node];
    int e1 = g_rowstart[node + 1];
    #pragma unroll 4
    for (int t = e0 + half; t < e1; t += 2) {
        int2 ed = __ldg(&g_edge[t]);            // broadcast within half-warp
        float c = __int_as_float(ed.y);
        float4 v = __ldg(&x4[(size_t)ed.x * 16 + hl]);
        acc.x = fmaf(v.x, c, acc.x);
        acc.y = fmaf(v.y, c, acc.y);
        acc.z = fmaf(v.z, c, acc.z);
        acc.w = fmaf(v.w, c, acc.w);
    }
    __syncwarp();
    // combine the two halves
    acc.x += __shfl_xor_sync(0xffffffffu, acc.x, 16);
    acc.y += __shfl_xor_sync(0xffffffffu, acc.y, 16);
    acc.z += __shfl_xor_sync(0xffffffffu, acc.z, 16);
    acc.w += __shfl_xor_sync(0xffffffffu, acc.w, 16);

    // self-loop term + store (half 0 only)
    if (half == 0) {
        float dv = g_dinv[node], s2 = dv * dv;
        float4 xs = __ldg(&x4[(size_t)node * 16 + hl]);
        acc.x = fmaf(xs.x, s2, acc.x);
        acc.y = fmaf(xs.y, s2, acc.y);
        acc.z = fmaf(xs.z, s2, acc.z);
        acc.w = fmaf(xs.w, s2, acc.w);
        reinterpret_cast<float4*>(g_y)[(size_t)node * 16 + hl] = acc;
    }
}

// ---------------- packed GEMM + bias + GLU + residual ----------------
// 128 threads: thread j owns col pair (c, c+64), c = j&63; row-group q = j>>6
// handles RPB/2 rows. Weights packed in regs; y packed-dup in smem, read LDS.128.
__global__ void __launch_bounds__(128)
gemm_glu_kernel(const float* __restrict__ xin, float* __restrict__ xout,
                const float* __restrict__ W, const float* __restrict__ b,
                int n) {
    __shared__ unsigned long long ysp[RPB][C_IN];   // 32 KB: pack2(y,y)

    const int j = threadIdx.x;
    const int c = j & 63;
    const int q = j >> 6;                 // 0 or 1
    const int row0 = blockIdx.x * RPB;

    // stage y rows, duplicated into both packed lanes
    #pragma unroll
    for (int t = j; t < RPB * C_IN; t += 128) {
        int r = t >> 6, k = t & 63;
        int row = row0 + r;
        float v = (row < n) ? g_y[(size_t)row * C_IN + k] : 0.0f;
        ysp[r][k] = pack2(v, v);
    }

    // weight column pair into registers
    unsigned long long wp[C_IN];
    #pragma unroll
    for (int k = 0; k < C_IN; k++)
        wp[k] = pack2(W[k * C_OUT + c], W[k * C_OUT + c + 64]);
    const unsigned long long bb = pack2(b[c], b[c + 64]);

    __syncthreads();

    #pragma unroll 2
    for (int rr = 0; rr < RPB / 2; rr++) {
        int r = q * (RPB / 2) + rr;
        int row = row0 + r;
        const ulonglong2* yv = reinterpret_cast<const ulonglong2*>(&ysp[r][0]);
        unsigned long long a0 = bb, a1 = 0ull;
        #pragma unroll
        for (int k2 = 0; k2 < 32; k2++) {
            ulonglong2 yy = yv[k2];               // LDS.128 broadcast
            FMA_F32X2(a0, yy.x, wp[2 * k2 + 0], a0);
            FMA_F32X2(a1, yy.y, wp[2 * k2 + 1], a1);
        }
        unsigned long long at;
        ADD_F32X2(at, a0, a1);
        float av, gv;
        unpack2(at, av, gv);
        if (row < n) {
            float sig = 1.0f / (1.0f + expf(-gv));
            xout[(size_t)row * C_IN + c] =
                fmaf(av, sig, xin[(size_t)row * C_IN + c]);
        }
    }
}

extern "C" void kernel_launch(void* const* d_in, const int* in_sizes, int n_in,
                              void* d_out, int out_size) {
    // Identify inputs by SIZE:
    //   x: == out_size (6.4M f32); edge_index: largest rest (3.2M i32);
    //   Ws: next (24576 f32); bs: smallest (384 f32)
    const float* x = nullptr; const float* Ws = nullptr; const float* bs = nullptr;
    const int* ei = nullptr;
    int ei_elems = 0, Ws_elems = 0;
    int used[16] = {0};
    for (int i = 0; i < n_in; i++)
        if (!x && in_sizes[i] == out_size) { x = (const float*)d_in[i]; used[i] = 1; break; }
    {
        int best = -1, bsz = -1;
        for (int i = 0; i < n_in; i++)
            if (!used[i] && in_sizes[i] > bsz) { bsz = in_sizes[i]; best = i; }
        ei = (const int*)d_in[best]; ei_elems = bsz; used[best] = 1;
    }
    {
        int best = -1, bsz = -1;
        for (int i = 0; i < n_in; i++)
            if (!used[i] && in_sizes[i] > bsz) { bsz = in_sizes[i]; best = i; }
        Ws = (const float*)d_in[best]; Ws_elems = bsz; used[best] = 1;
    }
    for (int i = 0; i < n_in; i++)
        if (!used[i]) { bs = (const float*)d_in[i]; used[i] = 1; break; }

    const int n = out_size / C_IN;
    const int e = ei_elems / 2;
    const int L = Ws_elems / (C_IN * C_OUT);
    const int* src = ei;
    const int* dst = ei + e;
    const int nb = (n + 1023) / 1024;

    float *x0, *x1;
    cudaGetSymbolAddress((void**)&x0, g_x0);
    cudaGetSymbolAddress((void**)&x1, g_x1);

    // ---- CSR build (once per call) ----
    zero_cnt_kernel<<<(n + 255) / 256, 256>>>(n);
    count_kernel<<<(e + 255) / 256, 256>>>(dst, e, n);
    dinv_kernel<<<(n + 255) / 256, 256>>>(n);
    scan1_kernel<<<nb, 1024>>>(n);
    scan2_kernel<<<1, 32>>>(nb, n);
    scan3_kernel<<<nb, 1024>>>(n);
    zero_cnt_kernel<<<(n + 255) / 256, 256>>>(n);
    fill_kernel<<<(e + 255) / 256, 256>>>(src, dst, e, n);

    // ---- layers ----
    const float* xin = x;
    for (int l = 0; l < L; l++) {
        float* xout = (l == L - 1) ? (float*)d_out : ((l & 1) ? x1 : x0);
        agg_kernel<<<(n * 32 + 255) / 256, 256>>>(xin, n);
        gemm_glu_kernel<<<(n + RPB - 1) / RPB, 128>>>(
            xin, xout, Ws + (size_t)l * C_IN * C_OUT, bs + (size_t)l * C_OUT, n);
        xin = xout;
    }
}